// round 14
// baseline (speedup 1.0000x reference)
#include <cuda_runtime.h>
#include <cstddef>

// Problem constants (bigram trie, fixed shapes from reference)
#define V_  32768
#define C_  32
#define B_  32
#define K_  (V_ * C_)        // 1048576 bigram nodes
#define X_  (K_ + 1)         // pointers length
#define G_  V_               // unigram count
#define U_  (V_ + 1)         // first bigram node index

// Fully warp-autonomous fused fill + inline override. NO barriers, NO smem.
// Grid: 1024 blocks x 256 threads; each warp owns a 128-wide v-span of one row.
//  - every lane: float4 fill load + the uniform chain (coalesced/broadcast LDGs)
//  - lane j loads child j of the row's 32 children
//  - ballot over "child in my warp's span" (avg 0.125 hits) -> rare shfl
//    broadcast patches the owning lane's registers BEFORE the single store
__global__ void __launch_bounds__(256) llm_fused_kernel(
    const int* __restrict__ hist,
    const int* __restrict__ idx,
    const int* __restrict__ pointers,
    const int* __restrict__ ids,
    const float* __restrict__ logs,
    float* __restrict__ out)
{
    const int blk  = blockIdx.x;               // 0..1023
    const int b    = blk >> 5;                 // row (32 chunks per row)
    const int tid  = threadIdx.x;
    const int lane = tid & 31;
    const int v0   = (blk & 31) * 1024 + tid * 4;   // this thread's 4 v's
    const int w0   = v0 & ~127;                     // warp's 128-wide span base

    // Fill data, issued immediately.
    const float4 lv = *reinterpret_cast<const float4*>(logs + v0);

    // Uniform chain (broadcast loads, 1 transaction per warp each).
    const int h = __ldg(hist + (__ldg(idx) - 1) * B_ + b);
    const float backoff = __ldg(logs + (size_t)X_ + G_ + h);

    // Lane j owns child j of row b.
    const int off = __ldg(pointers + h);
    const int nc  = __ldg(pointers + h + 1) - off + 1;
    int   tok = -1;
    float lp  = 0.0f;
    if (lane < nc) {
        const int node = h + off + lane;            // bigram node id
        tok = __ldg(ids + (node - U_));             // child token id
        lp  = __ldg(logs + node);                   // bigram log-prob
    }

    float r0 = backoff + lv.x;
    float r1 = backoff + lv.y;
    float r2 = backoff + lv.z;
    float r3 = backoff + lv.w;

    // Which lanes hold a child landing in this warp's 128-v span?
    const bool in_span = (unsigned)(tok - w0) < 128u;
    unsigned mask = __ballot_sync(0xFFFFFFFFu, in_span);
    while (mask) {                                  // avg 0.125 iterations
        const int src = __ffs(mask) - 1;
        mask &= mask - 1;
        const int   btok = __shfl_sync(0xFFFFFFFFu, tok, src);
        const float blp  = __shfl_sync(0xFFFFFFFFu, lp,  src);
        const unsigned d = (unsigned)(btok - v0);
        if (d < 4u) {
            r0 = (d == 0u) ? blp : r0;
            r1 = (d == 1u) ? blp : r1;
            r2 = (d == 2u) ? blp : r2;
            r3 = (d == 3u) ? blp : r3;
        }
    }

    float4 o; o.x = r0; o.y = r1; o.z = r2; o.w = r3;
    *reinterpret_cast<float4*>(out + (size_t)b * V_ + v0) = o;
}

extern "C" void kernel_launch(void* const* d_in, const int* in_sizes, int n_in,
                              void* d_out, int out_size)
{
    const int*   hist     = (const int*)d_in[0];   // (S, B) int32
    const int*   idx      = (const int*)d_in[1];   // scalar int32
    const int*   pointers = (const int*)d_in[2];   // (X,) int32
    const int*   ids      = (const int*)d_in[3];   // (K,) int32
    const float* logs     = (const float*)d_in[4]; // (L,) float32
    float*       out      = (float*)d_out;         // (B, V) float32

    (void)in_sizes; (void)n_in; (void)out_size;

    llm_fused_kernel<<<(B_ * V_) / (256 * 4), 256>>>(hist, idx, pointers, ids, logs, out);
}

// round 15
// speedup vs baseline: 1.0417x; 1.0417x over previous
#include <cuda_runtime.h>
#include <cstddef>

// Problem constants (bigram trie, fixed shapes from reference)
#define V_  32768
#define C_  32
#define B_  32
#define K_  (V_ * C_)        // 1048576 bigram nodes
#define X_  (K_ + 1)         // pointers length
#define G_  V_               // unigram count
#define U_  (V_ + 1)         // first bigram node index

#define TPB     128          // threads per block
#define VCHUNK  (TPB * 4)    // 512-wide v-window per block
#define NCHUNK  (V_ / VCHUNK)// 64 chunks per row

// Fused fill + sparse override, warp-specialized, 128-thread blocks:
//  - grid = 2048 blocks (32 rows x 64 v-chunks), 4 warps/block
//  - warp 0 walks the uniform chain (idx -> h -> backoff/pointers -> ids/logs)
//    and broadcasts backoff via smem; warps 1..3 issue only their float4 load
//  - override operands prefetched pre-barrier; post-fill tail = 1 predicated STG
__global__ void __launch_bounds__(TPB) llm_fused_kernel(
    const int* __restrict__ hist,
    const int* __restrict__ idx,
    const int* __restrict__ pointers,
    const int* __restrict__ ids,
    const float* __restrict__ logs,
    float* __restrict__ out)
{
    __shared__ float s_back;

    const int blk   = blockIdx.x;          // 0..2047
    const int b     = blk >> 6;            // row (64 chunks per row)
    const int chunk = blk & 63;
    const int tid   = threadIdx.x;
    const int v0    = chunk * VCHUNK + tid * 4;
    float* __restrict__ row = out + (size_t)b * V_;

    // Every thread: its own fill data, issued immediately.
    const float4 lv = *reinterpret_cast<const float4*>(logs + v0);

    // Warp 0: uniform chain + override prefetch. Warps 1..3 go straight to
    // the barrier (their only load is already in flight).
    bool  ov_do  = false;
    int   ov_tok = 0;
    float ov_lp  = 0.0f;
    if (tid < 32) {
        const int h = __ldg(hist + (__ldg(idx) - 1) * B_ + b);
        const int off = __ldg(pointers + h);
        const int nc  = __ldg(pointers + h + 1) - off + 1;
        if (tid == 0)
            s_back = __ldg(logs + (size_t)X_ + G_ + h);
        if (tid < nc) {
            const int node = h + off + tid;           // bigram node id
            ov_tok = __ldg(ids + (node - U_));        // child token id
            ov_lp  = __ldg(logs + node);              // bigram log-prob
            ov_do  = (ov_tok >> 9) == chunk;          // in this block's 512-window
        }
    }

    __syncthreads();   // s_back ready (releases at depth-3 of warp-0 chain)

    const float backoff = s_back;
    float4 o;
    o.x = backoff + lv.x;
    o.y = backoff + lv.y;
    o.z = backoff + lv.z;
    o.w = backoff + lv.w;
    *reinterpret_cast<float4*>(row + v0) = o;

    __syncthreads();   // fill stores ordered before overrides

    if (ov_do)
        row[ov_tok] = ov_lp;
}

extern "C" void kernel_launch(void* const* d_in, const int* in_sizes, int n_in,
                              void* d_out, int out_size)
{
    const int*   hist     = (const int*)d_in[0];   // (S, B) int32
    const int*   idx      = (const int*)d_in[1];   // scalar int32
    const int*   pointers = (const int*)d_in[2];   // (X,) int32
    const int*   ids      = (const int*)d_in[3];   // (K,) int32
    const float* logs     = (const float*)d_in[4]; // (L,) float32
    float*       out      = (float*)d_out;         // (B, V) float32

    (void)in_sizes; (void)n_in; (void)out_size;

    llm_fused_kernel<<<B_ * NCHUNK, TPB>>>(hist, idx, pointers, ids, logs, out);
}

// round 16
// speedup vs baseline: 1.0922x; 1.0485x over previous
#include <cuda_runtime.h>
#include <cstddef>

// Problem constants (bigram trie, fixed shapes from reference)
#define V_  32768
#define C_  32
#define B_  32
#define K_  (V_ * C_)        // 1048576 bigram nodes
#define X_  (K_ + 1)         // pointers length
#define G_  V_               // unigram count
#define U_  (V_ + 1)         // first bigram node index

// Fused fill + sparse override, warp-specialized uniforms (best measured):
//  - grid = 1024 blocks (32 rows x 32 v-chunks), 256 threads, 1 float4/thread
//  - warp 0 alone walks the dependent chain (idx -> h -> backoff/pointers ->
//    ids/logs[node]) and broadcasts backoff via smem; warps 1..7 issue only
//    their logs[v] float4 load, so barrier 1 releases at chain depth 3.
//  - override operands prefetched pre-barrier into warp-0 registers;
//    post-fill tail = one predicated scalar STG.
__global__ void __launch_bounds__(256) llm_fused_kernel(
    const int* __restrict__ hist,
    const int* __restrict__ idx,
    const int* __restrict__ pointers,
    const int* __restrict__ ids,
    const float* __restrict__ logs,
    float* __restrict__ out)
{
    __shared__ float s_back;

    const int blk   = blockIdx.x;          // 0..1023
    const int b     = blk >> 5;            // row (32 chunks per row)
    const int chunk = blk & 31;
    const int tid   = threadIdx.x;
    const int v0    = chunk * 1024 + tid * 4;
    float* __restrict__ row = out + (size_t)b * V_;

    // Every thread: its own fill data, issued immediately.
    const float4 lv = *reinterpret_cast<const float4*>(logs + v0);

    // Warp 0: uniform chain + override prefetch. Other warps skip straight
    // to the barrier (their only load is already in flight).
    bool  ov_do  = false;
    int   ov_tok = 0;
    float ov_lp  = 0.0f;
    if (tid < 32) {
        const int h = __ldg(hist + (__ldg(idx) - 1) * B_ + b);
        const int off = __ldg(pointers + h);
        const int nc  = __ldg(pointers + h + 1) - off + 1;
        if (tid == 0)
            s_back = __ldg(logs + (size_t)X_ + G_ + h);
        if (tid < nc) {
            const int node = h + off + tid;           // bigram node id
            ov_tok = __ldg(ids + (node - U_));        // child token id
            ov_lp  = __ldg(logs + node);              // bigram log-prob
            ov_do  = (ov_tok >> 10) == chunk;         // in this block's window
        }
    }

    __syncthreads();   // s_back ready

    const float backoff = s_back;
    float4 o;
    o.x = backoff + lv.x;
    o.y = backoff + lv.y;
    o.z = backoff + lv.z;
    o.w = backoff + lv.w;
    *reinterpret_cast<float4*>(row + v0) = o;

    __syncthreads();   // fill stores ordered before overrides

    if (ov_do)
        row[ov_tok] = ov_lp;
}

extern "C" void kernel_launch(void* const* d_in, const int* in_sizes, int n_in,
                              void* d_out, int out_size)
{
    const int*   hist     = (const int*)d_in[0];   // (S, B) int32
    const int*   idx      = (const int*)d_in[1];   // scalar int32
    const int*   pointers = (const int*)d_in[2];   // (X,) int32
    const int*   ids      = (const int*)d_in[3];   // (K,) int32
    const float* logs     = (const float*)d_in[4]; // (L,) float32
    float*       out      = (float*)d_out;         // (B, V) float32

    (void)in_sizes; (void)n_in; (void)out_size;

    llm_fused_kernel<<<(B_ * V_) / (256 * 4), 256>>>(hist, idx, pointers, ids, logs, out);
}